// round 10
// baseline (speedup 1.0000x reference)
#include <cuda_runtime.h>
#include <cuda_bf16.h>
#include <cstdint>

// DepthToSpace: x [8, 64, 256, 256] fp32 -> out [8, 4, 1024, 1024] fp32
// out[b, s, 4h+r, 4w+c] = x[b, 16s+4r+c, h, w]
//
// R8: 256-bit access formulation (required by sm_103a ptxas for L2 evict
// hints) with per-warp smem transpose.
//  - loads : ld.global.L2::evict_last.v8.b32  — pin the 128MB read-only input
//            in the 126MB L2 across graph replays. Lane l loads ch_c[8l..8l+7];
//            per instruction the warp covers 1KB contiguous (coalesced).
//  - smem  : 4KB tile per warp, XOR swizzle  A = L ^ (bit7(L)<<4)  makes both
//            the STS.128 write phase and the LDS.64 transpose-read phase
//            bank-conflict-free (verified: 8-lane 128b phases -> banks
//            {0,8,16,24,4,12,20,28}; 16-lane 64b phases -> distinct even banks).
//  - stores: st.global.L2::evict_first.v4.b64 — output streams through L2
//            without displacing the pinned input. Lane stride 32B, warp writes
//            1KB contiguous per instruction (coalesced).

static __device__ __forceinline__ unsigned long long pack2(float lo, float hi) {
    return (unsigned long long)__float_as_uint(lo)
         | ((unsigned long long)__float_as_uint(hi) << 32);
}

__global__ __launch_bounds__(256, 6)
void depth_to_space_kernel(const float* __restrict__ x,
                           float4* __restrict__ out4)
{
    __shared__ float sm[8 * 1024];   // 4KB tile per warp, 8 warps

    const unsigned lane  = threadIdx.x & 31;
    const unsigned warp  = threadIdx.x >> 5;
    const unsigned row_g = blockIdx.x * 8 + warp;   // output row id, 0..32767

    const unsigned orow = row_g & 1023;             // row within (b,s) plane
    const unsigned bs   = row_g >> 10;              // b*4 + s
    const unsigned h    = orow >> 2;                // input spatial row
    const unsigned r    = orow & 3;                 // intra-cell row
    const unsigned ch0  = bs * 16 + r * 4;          // first of 4 input channels

    char* wbase = (char*)sm + warp * 4096;
    const float* gbase = x + (ch0 << 16) + (h << 8) + 8u * lane;

    // Phase A/B: 256-bit evict_last loads -> swizzled smem tile[4][256]
    #pragma unroll
    for (int c = 0; c < 4; c++) {
        unsigned r0, r1, r2, r3, r4, r5, r6, r7;
        const float* p = gbase + (c << 16);
        asm volatile(
            "ld.global.L2::evict_last.v8.b32 {%0,%1,%2,%3,%4,%5,%6,%7}, [%8];"
            : "=r"(r0), "=r"(r1), "=r"(r2), "=r"(r3),
              "=r"(r4), "=r"(r5), "=r"(r6), "=r"(r7)
            : "l"(p));

        const unsigned L0 = c * 1024u + lane * 32u;       // logical byte offset
        const unsigned A0 = L0 ^ ((L0 >> 3) & 16u);       // swizzle bit7->bit4
        const unsigned L1 = L0 + 16u;
        const unsigned A1 = L1 ^ ((L1 >> 3) & 16u);
        *(uint4*)(wbase + A0) = make_uint4(r0, r1, r2, r3);
        *(uint4*)(wbase + A1) = make_uint4(r4, r5, r6, r7);
    }
    __syncwarp();

    // Phase D: transpose-read + 256-bit evict_first stores.
    // Lane handles output float4 pairs (w, w+1), w = 2*lane + 64*k.
    const size_t orow_byte = (size_t)row_g * 4096u;       // row start in bytes
    #pragma unroll
    for (int k = 0; k < 4; k++) {
        const unsigned w = 2u * lane + 64u * k;
        float2 f[4];
        #pragma unroll
        for (int c = 0; c < 4; c++) {
            const unsigned L = c * 1024u + 4u * w;        // 8B-aligned
            const unsigned A = L ^ ((L >> 3) & 16u);
            f[c] = *(const float2*)(wbase + A);           // (ch_c[w], ch_c[w+1])
        }
        const unsigned long long u0 = pack2(f[0].x, f[1].x);  // float4 #w  .xy
        const unsigned long long u1 = pack2(f[2].x, f[3].x);  // float4 #w  .zw
        const unsigned long long u2 = pack2(f[0].y, f[1].y);  // float4 #w+1.xy
        const unsigned long long u3 = pack2(f[2].y, f[3].y);  // float4 #w+1.zw

        char* po = (char*)out4 + orow_byte + (size_t)w * 16u; // 32B aligned (w even)
        asm volatile(
            "st.global.L2::evict_first.v4.b64 [%0], {%1,%2,%3,%4};"
            :: "l"(po), "l"(u0), "l"(u1), "l"(u2), "l"(u3)
            : "memory");
    }
}

extern "C" void kernel_launch(void* const* d_in, const int* in_sizes, int n_in,
                              void* d_out, int out_size)
{
    const float* x  = (const float*)d_in[0];
    float4*      o4 = (float4*)d_out;

    // 32768 output rows / 8 rows per block
    depth_to_space_kernel<<<4096, 256>>>(x, o4);
}

// round 13
// speedup vs baseline: 1.0376x; 1.0376x over previous
#include <cuda_runtime.h>
#include <cuda_bf16.h>
#include <cstdint>

// DepthToSpace: x [8, 64, 256, 256] fp32 -> out [8, 4, 1024, 1024] fp32
// out[b, s, 4h+r, 4w+c] = x[b, 16s+4r+c, h, w]
//
// R10: R5's direct store-coalesced structure (best: 36.1us kernel, DRAM 74.5%)
// made PERSISTENT. R5 ran 16384 one-shot blocks (~13.8 waves at 8 blocks/SM);
// every freshly spawned block paid a ~600-1000 cycle DRAM-latency ramp with no
// loads in flight (~15-20% of each ~2.6us wave) — that accounts for the missing
// DRAM utilization. Here: exactly one wave (1184 blocks = 8/SM x 148 SM), each
// thread grid-strides over ~14 tiles. Iteration i+1 loads are independent of
// iteration i stores, so warps stream loads continuously; the ramp is paid once.
//
// Tile (unchanged from R5): thread produces 2 consecutive-by-32 output float4s.
//   - stores: consecutive lanes -> consecutive float4  => coalesced STG.128
//   - loads:  consecutive lanes -> consecutive 4B per channel => 128B wavefronts

static constexpr unsigned NT          = 1u << 22;      // 4,194,304 tiles (threads' worth)
static constexpr unsigned NBLOCKS     = 148 * 8;       // one full wave
static constexpr unsigned NTHREADS    = 256;
static constexpr unsigned GRID_STRIDE = NBLOCKS * NTHREADS;  // 303,104 (mult. of 32)

__global__ __launch_bounds__(NTHREADS, 8)
void depth_to_space_kernel(const float* __restrict__ x,
                           float4* __restrict__ out4)
{
    const unsigned tid0 = blockIdx.x * NTHREADS + threadIdx.x;
    const unsigned lane = tid0 & 31;                   // invariant across iters

    for (unsigned t = tid0; t < NT; t += GRID_STRIDE) {
        const unsigned wid      = t >> 5;              // warp-tile id
        const unsigned ofi_base = wid * 64;            // output float4 base of warp

        const unsigned orow = (ofi_base >> 8) & 1023;  // output row within (b,s)
        const unsigned bs   =  ofi_base >> 18;         // b*4 + s, 0..31
        const unsigned h    = orow >> 2;               // input spatial row
        const unsigned r    = orow & 3;                // intra-cell row
        const unsigned ch0  = bs * 16 + r * 4;         // first of 4 input channels

        const unsigned w0   = (ofi_base & 255) + lane;     // col for k=0
        const unsigned in_a = (ch0 << 16) + (h << 8) + w0; // scalar idx, < 2^24
        const unsigned CH   = 1u << 16;                    // channel stride (floats)

        float v[2][4];
        #pragma unroll
        for (int k = 0; k < 2; k++) {
            const unsigned a = in_a + 32u * k;
            #pragma unroll
            for (int c = 0; c < 4; c++)
                v[k][c] = x[a + c * CH];
        }

        const unsigned ob = ofi_base + lane;
        #pragma unroll
        for (int k = 0; k < 2; k++)
            out4[ob + 32u * k] = make_float4(v[k][0], v[k][1], v[k][2], v[k][3]);
    }
}

extern "C" void kernel_launch(void* const* d_in, const int* in_sizes, int n_in,
                              void* d_out, int out_size)
{
    const float* x  = (const float*)d_in[0];
    float4*      o4 = (float4*)d_out;

    depth_to_space_kernel<<<NBLOCKS, NTHREADS>>>(x, o4);
}

// round 16
// speedup vs baseline: 1.0858x; 1.0464x over previous
#include <cuda_runtime.h>
#include <cuda_bf16.h>
#include <cstdint>

// DepthToSpace: x [8, 64, 256, 256] fp32 -> out [8, 4, 1024, 1024] fp32
// out[b, s, 4h+r, 4w+c] = x[b, 16s+4r+c, h, w]
//
// R13 = R5 (best: 36.1us kernel / 44.9us bench) with 128-thread blocks.
//
// Why stop structural search: in the timed loop the kernel moves the full
// 256MB/replay (the ncu "74% DRAM" is a cold-cache artifact — ~55MB of dirty
// output writebacks outlive the profiled launch and go uncounted). At 36.1us
// that is ~7.1TB/s = ~89% of the 8TB/s spec, i.e. at the mixed-R/W HBM
// turnaround ceiling. Falsified alternatives: .cs input stream (R6), L2
// pin-input/stream-output with 256-bit ops + smem transpose (R8), persistent
// one-wave grid (R10) — all flat or worse, as expected at the roofline.
//
// This round's single variable: block 256->128 (occupancy cap 8->16 blocks/SM)
// to shrink the scheduling tail (achieved occ was 80% of 100% theoretical).
// Memory pattern is warp-granular and byte-identical:
//   - stores: consecutive lanes -> consecutive float4  => coalesced STG.128
//   - loads:  consecutive lanes -> consecutive 4B per channel => one 128B
//             line per LDG instruction per warp
//   - per thread: 8 front-batched scalar loads, 2 STG.128 (regs=18, no spill)

__global__ __launch_bounds__(128, 16)
void depth_to_space_kernel(const float* __restrict__ x,
                           float4* __restrict__ out4)
{
    const unsigned t    = blockIdx.x * blockDim.x + threadIdx.x;  // 0 .. 4194303
    const unsigned lane = t & 31;
    const unsigned wid  = t >> 5;                                 // 0 .. 131071

    // This warp covers output-float4 indices [wid*64, wid*64+64).
    const unsigned ofi_base = wid * 64;
    const unsigned orow = (ofi_base >> 8) & 1023;   // output row within (b,s)
    const unsigned bs   =  ofi_base >> 18;          // b*4 + s, 0..31

    const unsigned h   = orow >> 2;                 // input spatial row
    const unsigned r   = orow & 3;                  // intra-cell row
    const unsigned ch0 = bs * 16 + r * 4;           // first of 4 input channels

    const unsigned w0   = (ofi_base & 255) + lane;       // col for k=0
    const unsigned in_a = (ch0 << 16) + (h << 8) + w0;   // scalar index, < 2^24
    const unsigned CH   = 1u << 16;                      // channel stride (floats)

    float v[2][4];
    #pragma unroll
    for (int k = 0; k < 2; k++) {
        const unsigned a = in_a + 32u * k;
        #pragma unroll
        for (int c = 0; c < 4; c++)
            v[k][c] = x[a + c * CH];
    }

    const unsigned ob = ofi_base + lane;
    #pragma unroll
    for (int k = 0; k < 2; k++)
        out4[ob + 32u * k] = make_float4(v[k][0], v[k][1], v[k][2], v[k][3]);
}

extern "C" void kernel_launch(void* const* d_in, const int* in_sizes, int n_in,
                              void* d_out, int out_size)
{
    const float* x  = (const float*)d_in[0];
    float4*      o4 = (float4*)d_out;

    // 8,388,608 output float4s / 2 per thread = 4,194,304 threads
    const int threads = 128;
    const int blocks  = 32768;
    depth_to_space_kernel<<<blocks, threads>>>(x, o4);
}

// round 17
// speedup vs baseline: 1.1353x; 1.0456x over previous
#include <cuda_runtime.h>
#include <cuda_bf16.h>
#include <cstdint>

// DepthToSpace: x [8, 64, 256, 256] fp32 -> out [8, 4, 1024, 1024] fp32
// out[b, s, 4h+r, 4w+c] = x[b, 16s+4r+c, h, w]
//
// R16 = best-known structure (R5/R6: 2 output float4 per thread, direct, no
// hints, no smem) with block size as the single variable: 256 -> 512.
// Evidence: block-size sweep shows 128t -> 41.5us (L1 68%, queue churn),
// 256t -> 36.1us (best). Same warps/SM either way; larger blocks reduce CTA
// dispatch churn and smooth the L1tex stream. 512t is the last untested point
// on the only axis with measured signal.
//
// Steady-state model: 256MB/replay at 36.1us = ~7.1TB/s = ~89% of spec —
// at the mixed-R/W HBM turnaround ceiling. Falsified: .cs streaming (R6),
// L2 evict-hint pin/stream + 256-bit + smem transpose (R8), persistent
// one-wave grid (R10), 128t blocks (R13).
//
//   - stores: consecutive lanes -> consecutive float4  => coalesced STG.128
//   - loads:  consecutive lanes -> consecutive 4B per channel => one 128B
//             line per LDG per warp
//   - per thread: 8 front-batched scalar loads, 2 STG.128 (regs=18, no spill)

__global__ __launch_bounds__(512, 4)
void depth_to_space_kernel(const float* __restrict__ x,
                           float4* __restrict__ out4)
{
    const unsigned t    = blockIdx.x * blockDim.x + threadIdx.x;  // 0 .. 4194303
    const unsigned lane = t & 31;
    const unsigned wid  = t >> 5;                                 // 0 .. 131071

    // This warp covers output-float4 indices [wid*64, wid*64+64).
    const unsigned ofi_base = wid * 64;
    const unsigned orow = (ofi_base >> 8) & 1023;   // output row within (b,s)
    const unsigned bs   =  ofi_base >> 18;          // b*4 + s, 0..31

    const unsigned h   = orow >> 2;                 // input spatial row
    const unsigned r   = orow & 3;                  // intra-cell row
    const unsigned ch0 = bs * 16 + r * 4;           // first of 4 input channels

    const unsigned w0   = (ofi_base & 255) + lane;       // col for k=0
    const unsigned in_a = (ch0 << 16) + (h << 8) + w0;   // scalar index, < 2^24
    const unsigned CH   = 1u << 16;                      // channel stride (floats)

    float v[2][4];
    #pragma unroll
    for (int k = 0; k < 2; k++) {
        const unsigned a = in_a + 32u * k;
        #pragma unroll
        for (int c = 0; c < 4; c++)
            v[k][c] = x[a + c * CH];
    }

    const unsigned ob = ofi_base + lane;
    #pragma unroll
    for (int k = 0; k < 2; k++)
        out4[ob + 32u * k] = make_float4(v[k][0], v[k][1], v[k][2], v[k][3]);
}

extern "C" void kernel_launch(void* const* d_in, const int* in_sizes, int n_in,
                              void* d_out, int out_size)
{
    const float* x  = (const float*)d_in[0];
    float4*      o4 = (float4*)d_out;

    // 8,388,608 output float4s / 2 per thread = 4,194,304 threads
    const int threads = 512;
    const int blocks  = 8192;
    depth_to_space_kernel<<<blocks, threads>>>(x, o4);
}